// round 6
// baseline (speedup 1.0000x reference)
#include <cuda_runtime.h>
#include <cstdint>
#include <cstddef>

// Problem constants
#define NF   131072
#define INS  256
#define HID  1024
#define OUTS 256
#define NE   16
#define TM   128
#define HC   32
#define NCHUNK (HID / HC)        // 32
#define GRID2 (NF / TM + NE)     // 1040

typedef unsigned int u32;
typedef unsigned long long u64;

// ---------------- routing scratch ----------------
__device__ int g_cnt[NE];
__device__ int g_off[NE + 1];
__device__ int g_cur[NE];
__device__ int g_tile[NE + 1];
__device__ int g_perm[NF];
__device__ int g_ids_is64;
__device__ int g_done;

__device__ __forceinline__ int get_id(const void* ids, int i, int is64) {
    int e = is64 ? (int)((const long long*)ids)[i] : ((const int*)ids)[i];
    return e & 15;
}

// ---------------- launch 1: dtype probe + zero ----------------
__global__ void k_init(const long long* __restrict__ ids) {
    __shared__ int bad;
    if (threadIdx.x == 0) bad = 0;
    __syncthreads();
    for (int i = threadIdx.x; i < 4096; i += 256) {
        unsigned long long v = (unsigned long long)ids[i];
        if (v > 15ULL) bad = 1;
    }
    __syncthreads();
    if (threadIdx.x == 0) { g_ids_is64 = bad ? 0 : 1; g_done = 0; }
    if (threadIdx.x < NE) g_cnt[threadIdx.x] = 0;
}

// ---------------- launch 2: histogram, last block scans ----------------
__global__ void k_count_scan(const void* __restrict__ ids) {
    __shared__ int h[NE];
    __shared__ int lastf;
    int tid = threadIdx.x;
    if (tid < NE) h[tid] = 0;
    __syncthreads();
    int is64 = g_ids_is64;
    int base = blockIdx.x * 512;
    atomicAdd(&h[get_id(ids, base + tid, is64)], 1);
    atomicAdd(&h[get_id(ids, base + 256 + tid, is64)], 1);
    __syncthreads();
    if (tid < NE) atomicAdd(&g_cnt[tid], h[tid]);
    __threadfence();
    if (tid == 0) lastf = (atomicAdd(&g_done, 1) == 255);
    __syncthreads();
    if (lastf && tid == 0) {
        int o = 0, t = 0;
        for (int e = 0; e < NE; e++) {
            g_off[e] = o; g_cur[e] = o; g_tile[e] = t;
            o += g_cnt[e];
            t += (g_cnt[e] + TM - 1) / TM;
        }
        g_off[NE] = o; g_tile[NE] = t;
    }
}

// ---------------- launch 3: scatter ----------------
__global__ void k_scatter(const void* __restrict__ ids) {
    __shared__ int h[NE], bm[NE];
    int tid = threadIdx.x;
    if (tid < NE) h[tid] = 0;
    __syncthreads();
    int is64 = g_ids_is64;
    int base = blockIdx.x * 512;
    int e0 = get_id(ids, base + tid, is64);
    int e1 = get_id(ids, base + 256 + tid, is64);
    atomicAdd(&h[e0], 1);
    atomicAdd(&h[e1], 1);
    __syncthreads();
    if (tid < NE) { bm[tid] = atomicAdd(&g_cur[tid], h[tid]); h[tid] = 0; }
    __syncthreads();
    int r0 = atomicAdd(&h[e0], 1); g_perm[bm[e0] + r0] = base + tid;
    int r1 = atomicAdd(&h[e1], 1); g_perm[bm[e1] + r1] = base + 256 + tid;
}

// ---------------- helpers ----------------
__device__ __forceinline__ u32 f2tf32(float f) {
    u32 u; asm("cvt.rna.tf32.f32 %0, %1;" : "=r"(u) : "f"(f)); return u;
}
__device__ __forceinline__ u32 smem_u32(const void* p) {
    u32 a;
    asm("{ .reg .u64 t; cvta.to.shared.u64 t, %1; cvt.u32.u64 %0, t; }" : "=r"(a) : "l"(p));
    return a;
}
__device__ __forceinline__ void cpa16(u32 dst, const void* src) {
    asm volatile("cp.async.cg.shared.global [%0], [%1], 16;" :: "r"(dst), "l"(src));
}
#define CPA_COMMIT() asm volatile("cp.async.commit_group;" ::: "memory")
#define CPA_WAIT1()  asm volatile("cp.async.wait_group 1;" ::: "memory")

__device__ __forceinline__ void mma8(float* d, const u32* a, const u32* b) {
    asm volatile("mma.sync.aligned.m16n8k8.row.col.f32.tf32.tf32.f32 "
        "{%0,%1,%2,%3}, {%4,%5,%6,%7}, {%8,%9}, {%0,%1,%2,%3};"
        : "+f"(d[0]), "+f"(d[1]), "+f"(d[2]), "+f"(d[3])
        : "r"(a[0]), "r"(a[1]), "r"(a[2]), "r"(a[3]), "r"(b[0]), "r"(b[1]));
}

// ---------------- SMEM layout (u32 element offsets) ----------------
// sXp  [128][132 u64]  X tile as (k,k+4) tf32 pairs; row stride 264 u32   135168 B
// sW1r [256][32]       raw fp32 W1 chunk, k-XOR swizzled                   32768 B
// sW2r [32][256]       raw fp32 W2 chunk, k-XOR swizzled                   32768 B
// sH   [128][40]       tf32 h tile                                         20480 B
// sb2[256], toks[128]
#define XPS  264     // u32 stride per X row (132 u64)
#define HSd  40
#define OFF_X    0
#define OFF_W1   33792
#define OFF_W2   41984
#define OFF_H    50176
#define OFF_B2   55296
#define OFF_TOKS 55552
#define SMEM_U32 55680
#define SMEM_BYTES (SMEM_U32 * 4)    // 222720

__global__ void __launch_bounds__(256, 1)
k_mlp(const float* __restrict__ X,  const float* __restrict__ W1,
      const float* __restrict__ B1v, const float* __restrict__ W2,
      const float* __restrict__ B2v, float* __restrict__ Y)
{
    extern __shared__ u32 smu[];
    u32*   sXp  = smu + OFF_X;
    u32*   sW1r = smu + OFF_W1;
    u32*   sW2r = smu + OFF_W2;
    u32*   sH   = smu + OFF_H;
    float* sb2  = (float*)(smu + OFF_B2);
    int*   toks = (int*)(smu + OFF_TOKS);
    u32 sbase = smem_u32(smu);

    int tid  = threadIdx.x;
    int wid  = tid >> 5;
    int lane = tid & 31;
    int gid  = lane >> 2;
    int tig  = lane & 3;
    int m0  = (wid & 3) * 32;      // GEMM1: 4 m x 2 n
    int n0  = (wid >> 2) * 16;
    int m02 = (wid & 1) * 64;      // GEMM2: 2 m x 4 n
    int n02 = (wid >> 1) * 64;
    u32 swz = (u32)(tig << 3);

    int bid = blockIdx.x;
    if (bid >= g_tile[NE]) return;
    int e = 0;
    while (bid >= g_tile[e + 1]) e++;
    int goff = g_off[e];
    int cnt  = g_off[e + 1] - goff;
    int t0   = (bid - g_tile[e]) * TM;
    int vcnt = min(TM, cnt - t0);

    const float* w1e = W1  + (size_t)e * INS * HID;
    const float* w2e = W2  + (size_t)e * HID * OUTS;
    const float* b1e = B1v + (size_t)e * HID;

    // ---- Prologue: cp.async W1(0), W2(0) ----
    {
        #pragma unroll
        for (int i = 0; i < 8; i++) {
            int idx = i * 256 + tid;
            int k = idx >> 3, c = idx & 7;
            int c2 = c ^ ((k & 3) << 1);
            cpa16(sbase + (OFF_W1 + k * 32 + c2 * 4) * 4, w1e + (size_t)k * HID + c * 4);
        }
        CPA_COMMIT();
        #pragma unroll
        for (int i = 0; i < 8; i++) {
            int idx = i * 256 + tid;
            int k = idx >> 6, c = idx & 63;
            int c2 = c ^ ((k & 3) << 1);
            cpa16(sbase + (OFF_W2 + k * 256 + c2 * 4) * 4, w2e + (size_t)k * OUTS + c * 4);
        }
        CPA_COMMIT();
    }

    if (tid < TM) {
        int slot = t0 + tid;
        if (slot >= cnt) slot = cnt - 1;
        toks[tid] = g_perm[goff + slot];
    }
    sb2[tid] = B2v[(size_t)e * OUTS + tid];
    __syncthreads();

    // ---- Load X tile into (k,k+4) u64-pair layout ----
    // pair index p = c*4 + t holds (tf32 x[8c+t], tf32 x[8c+t+4])
    #pragma unroll 4
    for (int it = 0; it < 16; it++) {
        int g = it * 256 + tid;    // 4096 groups of 8 k
        int r = g >> 5;
        int c = g & 31;
        const float* xr = X + (size_t)toks[r] * INS + c * 8;
        float4 va = *(const float4*)xr;
        float4 vb = *(const float4*)(xr + 4);
        uint4 p01 = { f2tf32(va.x), f2tf32(vb.x), f2tf32(va.y), f2tf32(vb.y) };
        uint4 p23 = { f2tf32(va.z), f2tf32(vb.z), f2tf32(va.w), f2tf32(vb.w) };
        *(uint4*)&sXp[r * XPS + c * 8]     = p01;
        *(uint4*)&sXp[r * XPS + c * 8 + 4] = p23;
    }

    float yacc[4][8][4];
    #pragma unroll
    for (int mt = 0; mt < 4; mt++)
        #pragma unroll
        for (int nb = 0; nb < 8; nb++)
            #pragma unroll
            for (int j = 0; j < 4; j++) yacc[mt][nb][j] = 0.0f;

    for (int n = 0; n < NCHUNK; n++) {
        int h0 = n * HC;

        CPA_WAIT1();
        __syncthreads();

        float bv0 = b1e[h0 + n0 + 2 * tig];
        float bv1 = b1e[h0 + n0 + 2 * tig + 1];
        float bv2 = b1e[h0 + n0 + 8 + 2 * tig];
        float bv3 = b1e[h0 + n0 + 8 + 2 * tig + 1];

        // ---- GEMM1 ----
        float acc1[2][2][4];
        #pragma unroll
        for (int mt = 0; mt < 2; mt++)
            #pragma unroll
            for (int nb = 0; nb < 2; nb++)
                #pragma unroll
                for (int j = 0; j < 4; j++) acc1[mt][nb][j] = 0.0f;

        #pragma unroll 4
        for (int kt = 0; kt < 32; kt++) {
            int pofs = kt * 4 + tig;
            u32 a[2][4];
            #pragma unroll
            for (int mt = 0; mt < 2; mt++) {
                int r = m0 + 16 * mt + gid;
                uint2 A0 = *(const uint2*)&sXp[r * XPS + pofs * 2];
                uint2 A1 = *(const uint2*)&sXp[(r + 8) * XPS + pofs * 2];
                a[mt][0] = A0.x; a[mt][2] = A0.y;
                a[mt][1] = A1.x; a[mt][3] = A1.y;
            }
            int k0 = kt * 8;
            #pragma unroll
            for (int nb = 0; nb < 2; nb++) {
                u32 ci = (u32)(n0 + 8 * nb + gid) ^ swz;
                u32 r0w = sW1r[(k0 + tig) * 32 + ci];
                u32 r1w = sW1r[(k0 + tig + 4) * 32 + ci];
                u32 b[2] = { f2tf32(__uint_as_float(r0w)), f2tf32(__uint_as_float(r1w)) };
                mma8(acc1[0][nb], a[0], b);
                mma8(acc1[1][nb], a[1], b);
            }
        }

        // ---- Epilogue A: relu(h + b1) -> tf32 -> sH ----
        #pragma unroll
        for (int mt = 0; mt < 2; mt++) {
            int r = m0 + 16 * mt + gid;
            #pragma unroll
            for (int nb = 0; nb < 2; nb++) {
                int c = n0 + 8 * nb + 2 * tig;
                float ba = nb ? bv2 : bv0;
                float bb = nb ? bv3 : bv1;
                uint2 lo = { f2tf32(fmaxf(acc1[mt][nb][0] + ba, 0.0f)),
                             f2tf32(fmaxf(acc1[mt][nb][1] + bb, 0.0f)) };
                uint2 hi = { f2tf32(fmaxf(acc1[mt][nb][2] + ba, 0.0f)),
                             f2tf32(fmaxf(acc1[mt][nb][3] + bb, 0.0f)) };
                *(uint2*)&sH[r * HSd + c]       = lo;
                *(uint2*)&sH[(r + 8) * HSd + c] = hi;
            }
        }
        __syncthreads();

        // ---- Issue W1(n+1) ----
        if (n + 1 < NCHUNK) {
            int h1 = h0 + HC;
            #pragma unroll
            for (int i = 0; i < 8; i++) {
                int idx = i * 256 + tid;
                int k = idx >> 3, c = idx & 7;
                int c2 = c ^ ((k & 3) << 1);
                cpa16(sbase + (OFF_W1 + k * 32 + c2 * 4) * 4,
                      w1e + (size_t)k * HID + h1 + c * 4);
            }
        }
        CPA_COMMIT();

        CPA_WAIT1();
        __syncthreads();

        // ---- GEMM2 ----
        #pragma unroll
        for (int kt = 0; kt < 4; kt++) {
            int k0 = kt * 8;
            u32 ah[4][4];
            #pragma unroll
            for (int mt = 0; mt < 4; mt++) {
                int r = m02 + 16 * mt + gid;
                ah[mt][0] = sH[r * HSd + k0 + tig];
                ah[mt][1] = sH[(r + 8) * HSd + k0 + tig];
                ah[mt][2] = sH[r * HSd + k0 + tig + 4];
                ah[mt][3] = sH[(r + 8) * HSd + k0 + tig + 4];
            }
            #pragma unroll
            for (int nb = 0; nb < 8; nb++) {
                u32 ci = (u32)(n02 + 8 * nb + gid) ^ swz;
                u32 r0w = sW2r[(k0 + tig) * 256 + ci];
                u32 r1w = sW2r[(k0 + tig + 4) * 256 + ci];
                u32 b[2] = { f2tf32(__uint_as_float(r0w)), f2tf32(__uint_as_float(r1w)) };
                mma8(yacc[0][nb], ah[0], b);
                mma8(yacc[1][nb], ah[1], b);
                mma8(yacc[2][nb], ah[2], b);
                mma8(yacc[3][nb], ah[3], b);
            }
        }
        __syncthreads();

        // ---- Issue W2(n+1) ----
        if (n + 1 < NCHUNK) {
            int h1 = h0 + HC;
            #pragma unroll
            for (int i = 0; i < 8; i++) {
                int idx = i * 256 + tid;
                int k = idx >> 6, c = idx & 63;
                int c2 = c ^ ((k & 3) << 1);
                cpa16(sbase + (OFF_W2 + k * 256 + c2 * 4) * 4,
                      w2e + (size_t)(h1 + k) * OUTS + c * 4);
            }
        }
        CPA_COMMIT();
    }

    // ---- Final: Y + b2, masked scatter store ----
    #pragma unroll
    for (int mt = 0; mt < 4; mt++) {
        int  rA = m02 + 16 * mt + gid, rB = rA + 8;
        bool vA = rA < vcnt, vB = rB < vcnt;
        float* yA = Y + (size_t)toks[rA] * OUTS;
        float* yB = Y + (size_t)toks[rB] * OUTS;
        #pragma unroll
        for (int nb = 0; nb < 8; nb++) {
            int c = n02 + 8 * nb + 2 * tig;
            float ba = sb2[c], bb = sb2[c + 1];
            if (vA) { float2 v = { yacc[mt][nb][0] + ba, yacc[mt][nb][1] + bb }; *(float2*)(yA + c) = v; }
            if (vB) { float2 v = { yacc[mt][nb][2] + ba, yacc[mt][nb][3] + bb }; *(float2*)(yB + c) = v; }
        }
    }
}

// ---------------- launch ----------------
extern "C" void kernel_launch(void* const* d_in, const int* in_sizes, int n_in,
                              void* d_out, int out_size)
{
    (void)out_size;
    const float *X = 0, *W1 = 0, *B1 = 0, *W2 = 0, *B2 = 0;
    const void  *IDS = 0;
    for (int i = 0; i < n_in; i++) {
        switch (in_sizes[i]) {
            case 33554432: X = (const float*)d_in[i]; break;
            case 4194304:  if (!W1) W1 = (const float*)d_in[i];
                           else     W2 = (const float*)d_in[i];
                           break;
            case 16384:    B1 = (const float*)d_in[i]; break;
            case 4096:     B2 = (const float*)d_in[i]; break;
            case 131072:   IDS = d_in[i]; break;
            default: break;
        }
    }
    float* Y = (float*)d_out;

    cudaFuncSetAttribute(k_mlp, cudaFuncAttributeMaxDynamicSharedMemorySize, SMEM_BYTES);

    k_init<<<1, 256>>>((const long long*)IDS);
    k_count_scan<<<256, 256>>>(IDS);
    k_scatter<<<256, 256>>>(IDS);
    k_mlp<<<GRID2, 256, SMEM_BYTES>>>(X, W1, B1, W2, B2, Y);
}

// round 7
// speedup vs baseline: 1.1012x; 1.1012x over previous
#include <cuda_runtime.h>
#include <cstdint>
#include <cstddef>

#define NF   131072
#define INS  256
#define HID  1024
#define OUTS 256
#define NE   16
#define TM   128
#define HC   32
#define NCHUNK (HID / HC)
#define GRID2 (NF / TM + NE)

typedef unsigned int u32;

// ---------------- routing scratch ----------------
__device__ int g_cnt[NE];
__device__ int g_off[NE + 1];
__device__ int g_cur[NE];
__device__ int g_tile[NE + 1];
__device__ int g_perm[NF];
__device__ int g_ids_is64;
__device__ int g_done;

__device__ __forceinline__ int get_id(const void* ids, int i, int is64) {
    int e = is64 ? (int)((const long long*)ids)[i] : ((const int*)ids)[i];
    return e & 15;
}

__global__ void k_init(const long long* __restrict__ ids) {
    __shared__ int bad;
    if (threadIdx.x == 0) bad = 0;
    __syncthreads();
    for (int i = threadIdx.x; i < 4096; i += 256) {
        unsigned long long v = (unsigned long long)ids[i];
        if (v > 15ULL) bad = 1;
    }
    __syncthreads();
    if (threadIdx.x == 0) { g_ids_is64 = bad ? 0 : 1; g_done = 0; }
    if (threadIdx.x < NE) g_cnt[threadIdx.x] = 0;
}

__global__ void k_count_scan(const void* __restrict__ ids) {
    __shared__ int h[NE];
    __shared__ int lastf;
    int tid = threadIdx.x;
    if (tid < NE) h[tid] = 0;
    __syncthreads();
    int is64 = g_ids_is64;
    int base = blockIdx.x * 512;
    atomicAdd(&h[get_id(ids, base + tid, is64)], 1);
    atomicAdd(&h[get_id(ids, base + 256 + tid, is64)], 1);
    __syncthreads();
    if (tid < NE) atomicAdd(&g_cnt[tid], h[tid]);
    __threadfence();
    if (tid == 0) lastf = (atomicAdd(&g_done, 1) == 255);
    __syncthreads();
    if (lastf && tid == 0) {
        int o = 0, t = 0;
        for (int e = 0; e < NE; e++) {
            g_off[e] = o; g_cur[e] = o; g_tile[e] = t;
            o += g_cnt[e];
            t += (g_cnt[e] + TM - 1) / TM;
        }
        g_off[NE] = o; g_tile[NE] = t;
    }
}

__global__ void k_scatter(const void* __restrict__ ids) {
    __shared__ int h[NE], bm[NE];
    int tid = threadIdx.x;
    if (tid < NE) h[tid] = 0;
    __syncthreads();
    int is64 = g_ids_is64;
    int base = blockIdx.x * 512;
    int e0 = get_id(ids, base + tid, is64);
    int e1 = get_id(ids, base + 256 + tid, is64);
    atomicAdd(&h[e0], 1);
    atomicAdd(&h[e1], 1);
    __syncthreads();
    if (tid < NE) { bm[tid] = atomicAdd(&g_cur[tid], h[tid]); h[tid] = 0; }
    __syncthreads();
    int r0 = atomicAdd(&h[e0], 1); g_perm[bm[e0] + r0] = base + tid;
    int r1 = atomicAdd(&h[e1], 1); g_perm[bm[e1] + r1] = base + 256 + tid;
}

// ---------------- helpers ----------------
__device__ __forceinline__ u32 f2tf32(float f) {
    u32 u; asm("cvt.rna.tf32.f32 %0, %1;" : "=r"(u) : "f"(f)); return u;
}
__device__ __forceinline__ u32 smem_u32(const void* p) {
    u32 a;
    asm("{ .reg .u64 t; cvta.to.shared.u64 t, %1; cvt.u32.u64 %0, t; }" : "=r"(a) : "l"(p));
    return a;
}
__device__ __forceinline__ void cpa16(u32 dst, const void* src) {
    asm volatile("cp.async.cg.shared.global [%0], [%1], 16;" :: "r"(dst), "l"(src));
}
#define CPA_COMMIT() asm volatile("cp.async.commit_group;" ::: "memory")
#define CPA_WAIT1()  asm volatile("cp.async.wait_group 1;" ::: "memory")
#define CPA_WAIT0()  asm volatile("cp.async.wait_group 0;" ::: "memory")

__device__ __forceinline__ void mma8(float* d, const u32* a, const u32* b) {
    asm volatile("mma.sync.aligned.m16n8k8.row.col.f32.tf32.tf32.f32 "
        "{%0,%1,%2,%3}, {%4,%5,%6,%7}, {%8,%9}, {%0,%1,%2,%3};"
        : "+f"(d[0]), "+f"(d[1]), "+f"(d[2]), "+f"(d[3])
        : "r"(a[0]), "r"(a[1]), "r"(a[2]), "r"(a[3]), "r"(b[0]), "r"(b[1]));
}

// ---------------- SMEM layout (u32 offsets) ----------------
// sXp  [128][264]  X tile as (k,k+4) tf32 pairs            135168 B
// sW1r [256][32]   raw fp32 W1 chunk, k-XOR swizzled        32768 B
// sW2r [32][256]   raw fp32 W2 chunk, k-XOR swizzled        32768 B
// sH   [128][36]   tf32 h tile (banks 4*gid+tig: CF)        18432 B
// sb1a [1024]      full b1 for this expert                   4096 B
// sb2[256], toks[128]
#define XPS  264
#define HSd  36
#define OFF_X    0
#define OFF_W1   33792
#define OFF_W2   41984
#define OFF_H    50176
#define OFF_B1A  54784
#define OFF_B2   55808
#define OFF_TOKS 56064
#define SMEM_U32 56192
#define SMEM_BYTES (SMEM_U32 * 4)   // 224768

__global__ void __launch_bounds__(256, 1)
k_mlp(const float* __restrict__ X,  const float* __restrict__ W1,
      const float* __restrict__ B1v, const float* __restrict__ W2,
      const float* __restrict__ B2v, float* __restrict__ Y)
{
    extern __shared__ u32 smu[];
    u32*   sXp  = smu + OFF_X;
    u32*   sW1r = smu + OFF_W1;
    u32*   sW2r = smu + OFF_W2;
    u32*   sH   = smu + OFF_H;
    float* sb1a = (float*)(smu + OFF_B1A);
    float* sb2  = (float*)(smu + OFF_B2);
    int*   toks = (int*)(smu + OFF_TOKS);
    u32 sbase = smem_u32(smu);

    int tid  = threadIdx.x;
    int lane = tid & 31;
    int wid  = tid >> 5;
    int gid  = lane >> 2;
    int tig  = lane & 3;
    int m0  = (wid & 3) * 32;      // GEMM1: 4m x 2n
    int n0  = (wid >> 2) * 16;
    int m02 = (wid & 1) * 64;      // GEMM2: 2m x 4n
    int n02 = (wid >> 1) * 64;
    u32 swz = (u32)(tig << 3);

    int bid = blockIdx.x;
    if (bid >= g_tile[NE]) return;
    int e = 0;
    while (bid >= g_tile[e + 1]) e++;
    int goff = g_off[e];
    int cnt  = g_off[e + 1] - goff;
    int t0   = (bid - g_tile[e]) * TM;
    int vcnt = min(TM, cnt - t0);

    const float* w1e = W1  + (size_t)e * INS * HID;
    const float* w2e = W2  + (size_t)e * HID * OUTS;
    const float* b1e = B1v + (size_t)e * HID;

    // ---- Prologue: cp.async W1(0) [g0], W2(0) [g1] ----
    {
        #pragma unroll
        for (int i = 0; i < 8; i++) {
            int idx = i * 256 + tid;
            int k = idx >> 3, c = idx & 7;
            int c2 = c ^ ((k & 3) << 1);
            cpa16(sbase + (OFF_W1 + k * 32 + c2 * 4) * 4, w1e + (size_t)k * HID + c * 4);
        }
        CPA_COMMIT();
        #pragma unroll
        for (int i = 0; i < 8; i++) {
            int idx = i * 256 + tid;
            int k = idx >> 6, c = idx & 63;
            int c2 = c ^ ((k & 3) << 1);
            cpa16(sbase + (OFF_W2 + k * 256 + c2 * 4) * 4, w2e + (size_t)k * OUTS + c * 4);
        }
        CPA_COMMIT();
    }

    if (tid < TM) {
        int slot = t0 + tid;
        if (slot >= cnt) slot = cnt - 1;
        toks[tid] = g_perm[goff + slot];
    }
    sb2[tid] = B2v[(size_t)e * OUTS + tid];
    *(float4*)&sb1a[tid * 4] = *(const float4*)(b1e + tid * 4);   // full b1, once
    __syncthreads();

    // ---- Load X tile into (k,k+4) u64-pair layout ----
    #pragma unroll 4
    for (int it = 0; it < 16; it++) {
        int g = it * 256 + tid;
        int r = g >> 5;
        int c = g & 31;
        const float* xr = X + (size_t)toks[r] * INS + c * 8;
        float4 va = *(const float4*)xr;
        float4 vb = *(const float4*)(xr + 4);
        uint4 p01 = { f2tf32(va.x), f2tf32(vb.x), f2tf32(va.y), f2tf32(vb.y) };
        uint4 p23 = { f2tf32(va.z), f2tf32(vb.z), f2tf32(va.w), f2tf32(vb.w) };
        *(uint4*)&sXp[r * XPS + c * 8]     = p01;
        *(uint4*)&sXp[r * XPS + c * 8 + 4] = p23;
    }

    float yacc[4][8][4];
    #pragma unroll
    for (int mt = 0; mt < 4; mt++)
        #pragma unroll
        for (int nb = 0; nb < 8; nb++)
            #pragma unroll
            for (int j = 0; j < 4; j++) yacc[mt][nb][j] = 0.0f;

    // Precomputed GEMM1 addresses
    const int rA0 = (m0 + gid) * XPS;
    const int rA1 = (m0 + 8 + gid) * XPS;
    const int rA2 = (m0 + 16 + gid) * XPS;
    const int rA3 = (m0 + 24 + gid) * XPS;
    const u32 ci0 = (u32)(n0 + gid) ^ swz;
    const u32 ci1 = (u32)(n0 + 8 + gid) ^ swz;

#define G1_LOADA(buf, kt) do {                                         \
    int pq = (kt) * 8 + tig * 2;                                       \
    uint2 A00 = *(const uint2*)&sXp[rA0 + pq];                         \
    uint2 A01 = *(const uint2*)&sXp[rA1 + pq];                         \
    uint2 A10 = *(const uint2*)&sXp[rA2 + pq];                         \
    uint2 A11 = *(const uint2*)&sXp[rA3 + pq];                         \
    aX[buf][0][0]=A00.x; aX[buf][0][2]=A00.y;                          \
    aX[buf][0][1]=A01.x; aX[buf][0][3]=A01.y;                          \
    aX[buf][1][0]=A10.x; aX[buf][1][2]=A10.y;                          \
    aX[buf][1][1]=A11.x; aX[buf][1][3]=A11.y;                          \
} while (0)

#define G1_LOADB(buf, kt) do {                                         \
    int kk = (kt) * 8;                                                 \
    bW[buf][0] = sW1r[(kk + tig) * 32 + ci0];                          \
    bW[buf][1] = sW1r[(kk + tig + 4) * 32 + ci0];                      \
    bW[buf][2] = sW1r[(kk + tig) * 32 + ci1];                          \
    bW[buf][3] = sW1r[(kk + tig + 4) * 32 + ci1];                      \
} while (0)

#define G1_COMP(buf) do {                                              \
    u32 bf0[2] = { f2tf32(__uint_as_float(bW[buf][0])),                \
                   f2tf32(__uint_as_float(bW[buf][1])) };              \
    u32 bf1[2] = { f2tf32(__uint_as_float(bW[buf][2])),                \
                   f2tf32(__uint_as_float(bW[buf][3])) };              \
    mma8(acc1[0][0], aX[buf][0], bf0); mma8(acc1[1][0], aX[buf][1], bf0); \
    mma8(acc1[0][1], aX[buf][0], bf1); mma8(acc1[1][1], aX[buf][1], bf1); \
} while (0)

    for (int n = 0; n < NCHUNK; n++) {
        int h0 = n * HC;

        CPA_WAIT1();        // W1(n) landed
        __syncthreads();    // publish W1(n) (+X/toks/b1 on n=0); sH(n-1)/sW1 reads done

        // ---- GEMM1: software-pipelined, fully unrolled ----
        float acc1[2][2][4];
        #pragma unroll
        for (int mt = 0; mt < 2; mt++)
            #pragma unroll
            for (int nb = 0; nb < 2; nb++)
                #pragma unroll
                for (int j = 0; j < 4; j++) acc1[mt][nb][j] = 0.0f;

        {
            u32 aX[2][2][4];
            u32 bW[2][4];
            G1_LOADA(0, 0); G1_LOADB(0, 0);
            #pragma unroll
            for (int kt = 0; kt < 32; kt++) {
                int cur = kt & 1, nxt = cur ^ 1;
                int ktn = (kt + 1) & 31;     // wrap: last prefetch is redundant, harmless
                G1_LOADA(nxt, ktn);
                G1_LOADB(nxt, ktn);
                G1_COMP(cur);
            }
        }

        // ---- Epilogue A: relu(h + b1) -> tf32 -> sH ----
        #pragma unroll
        for (int mt = 0; mt < 2; mt++) {
            int r = m0 + 16 * mt + gid;
            #pragma unroll
            for (int nb = 0; nb < 2; nb++) {
                int c = n0 + 8 * nb + 2 * tig;
                float ba = sb1a[h0 + c], bb = sb1a[h0 + c + 1];
                uint2 lo = { f2tf32(fmaxf(acc1[mt][nb][0] + ba, 0.0f)),
                             f2tf32(fmaxf(acc1[mt][nb][1] + bb, 0.0f)) };
                uint2 hi = { f2tf32(fmaxf(acc1[mt][nb][2] + ba, 0.0f)),
                             f2tf32(fmaxf(acc1[mt][nb][3] + bb, 0.0f)) };
                *(uint2*)&sH[r * HSd + c]       = lo;
                *(uint2*)&sH[(r + 8) * HSd + c] = hi;
            }
        }

        CPA_WAIT0();        // W2(n) landed (only pending group at this point)
        __syncthreads();    // publish sH(n) + W2(n); sW1 free

        // ---- Issue W1(n+1) (overlaps GEMM2) ----
        if (n + 1 < NCHUNK) {
            int h1 = h0 + HC;
            #pragma unroll
            for (int i = 0; i < 8; i++) {
                int idx = i * 256 + tid;
                int k = idx >> 3, c = idx & 7;
                int c2 = c ^ ((k & 3) << 1);
                cpa16(sbase + (OFF_W1 + k * 32 + c2 * 4) * 4,
                      w1e + (size_t)k * HID + h1 + c * 4);
            }
        }
        CPA_COMMIT();

        // ---- GEMM2: Y[64r][64n]/warp += h @ W2chunk ----
        #pragma unroll
        for (int kt = 0; kt < 4; kt++) {
            int k0 = kt * 8;
            u32 ah[4][4];
            #pragma unroll
            for (int mt = 0; mt < 4; mt++) {
                int r = m02 + 16 * mt + gid;
                ah[mt][0] = sH[r * HSd + k0 + tig];
                ah[mt][1] = sH[(r + 8) * HSd + k0 + tig];
                ah[mt][2] = sH[r * HSd + k0 + tig + 4];
                ah[mt][3] = sH[(r + 8) * HSd + k0 + tig + 4];
            }
            #pragma unroll
            for (int nb = 0; nb < 8; nb++) {
                u32 ci = (u32)(n02 + 8 * nb + gid) ^ swz;
                u32 r0w = sW2r[(k0 + tig) * 256 + ci];
                u32 r1w = sW2r[(k0 + tig + 4) * 256 + ci];
                u32 b[2] = { f2tf32(__uint_as_float(r0w)), f2tf32(__uint_as_float(r1w)) };
                mma8(yacc[0][nb], ah[0], b);
                mma8(yacc[1][nb], ah[1], b);
                mma8(yacc[2][nb], ah[2], b);
                mma8(yacc[3][nb], ah[3], b);
            }
        }
        __syncthreads();    // sW2 free

        // ---- Issue W2(n+1) ----
        if (n + 1 < NCHUNK) {
            int h1 = h0 + HC;
            #pragma unroll
            for (int i = 0; i < 8; i++) {
                int idx = i * 256 + tid;
                int k = idx >> 6, c = idx & 63;
                int c2 = c ^ ((k & 3) << 1);
                cpa16(sbase + (OFF_W2 + k * 256 + c2 * 4) * 4,
                      w2e + (size_t)(h1 + k) * OUTS + c * 4);
            }
        }
        CPA_COMMIT();
    }

    // ---- Final: Y + b2, masked scatter store ----
    #pragma unroll
    for (int mt = 0; mt < 4; mt++) {
        int  rA = m02 + 16 * mt + gid, rB = rA + 8;
        bool vA = rA < vcnt, vB = rB < vcnt;
        float* yA = Y + (size_t)toks[rA] * OUTS;
        float* yB = Y + (size_t)toks[rB] * OUTS;
        #pragma unroll
        for (int nb = 0; nb < 8; nb++) {
            int c = n02 + 8 * nb + 2 * tig;
            float ba = sb2[c], bb = sb2[c + 1];
            if (vA) { float2 v = { yacc[mt][nb][0] + ba, yacc[mt][nb][1] + bb }; *(float2*)(yA + c) = v; }
            if (vB) { float2 v = { yacc[mt][nb][2] + ba, yacc[mt][nb][3] + bb }; *(float2*)(yB + c) = v; }
        }
    }
}

// ---------------- launch ----------------
extern "C" void kernel_launch(void* const* d_in, const int* in_sizes, int n_in,
                              void* d_out, int out_size)
{
    (void)out_size;
    const float *X = 0, *W1 = 0, *B1 = 0, *W2 = 0, *B2 = 0;
    const void  *IDS = 0;
    for (int i = 0; i < n_in; i++) {
        switch (in_sizes[i]) {
            case 33554432: X = (const float*)d_in[i]; break;
            case 4194304:  if (!W1) W1 = (const float*)d_in[i];
                           else     W2 = (const float*)d_in[i];
                           break;
            case 16384:    B1 = (const float*)d_in[i]; break;
            case 4096:     B2 = (const float*)d_in[i]; break;
            case 131072:   IDS = d_in[i]; break;
            default: break;
        }
    }
    float* Y = (float*)d_out;

    cudaFuncSetAttribute(k_mlp, cudaFuncAttributeMaxDynamicSharedMemorySize, SMEM_BYTES);

    k_init<<<1, 256>>>((const long long*)IDS);
    k_count_scan<<<256, 256>>>(IDS);
    k_scatter<<<256, 256>>>(IDS);
    k_mlp<<<GRID2, 256, SMEM_BYTES>>>(X, W1, B1, W2, B2, Y);
}